// round 2
// baseline (speedup 1.0000x reference)
#include <cuda_runtime.h>
#include <cstdint>

#define MAXN 4096

// Per-x-query: wa, wb, wc, bitcast(I)
__device__ float4 g_xw[MAXN];
// Per-y-query: h0, h2, h1, h3*ratio
__device__ float4 g_yw[MAXN];
__device__ int    g_yJ[MAXN];

__device__ __forceinline__ int searchsorted_inner(const float* __restrict__ axis, float q, int n) {
    // searchsorted(axis[1:n-1], q, side='left'): smallest idx in [0, n-2] with axis[1+idx] >= q
    int lo = 0, hi = n - 2;
    while (lo < hi) {
        int mid = (lo + hi) >> 1;
        if (axis[1 + mid] < q) lo = mid + 1; else hi = mid;
    }
    return lo;
}

__global__ void precompute_weights(const float* __restrict__ xaxis,
                                   const float* __restrict__ yaxis,
                                   const float* __restrict__ xs,
                                   const float* __restrict__ ys,
                                   int n) {
    int k = blockIdx.x * blockDim.x + threadIdx.x;
    if (k >= n) return;

    // ---- x direction ----
    {
        float q = xs[k];
        int I = searchsorted_inner(xaxis, q, n);
        float x0 = xaxis[I];
        float x1 = xaxis[I + 1];
        int i2 = (I + 2 < n) ? I + 2 : n - 1;     // defensive OOB clamp (domain keeps I+2 < n)
        float x2 = xaxis[i2];
        float dx = x1 - x0;
        float t  = (q - x0) / dx;
        float t2 = t * t, t3 = t2 * t;
        float h0 = 1.0f - 3.0f * t2 + 2.0f * t3;
        float h1 = t - 2.0f * t2 + t3;
        float h2 = 3.0f * t2 - 2.0f * t3;
        float h3 = t3 - t2;
        float r  = dx / (x2 - x1);
        float4 w;
        w.x = h0 - h1;               // weight on S[I]
        w.y = h1 + h2 - h3 * r;      // weight on S[I+1]
        w.z = h3 * r;                // weight on S[I+2]
        w.w = __int_as_float(I);
        g_xw[k] = w;
    }

    // ---- y direction ----
    {
        float q = ys[k];
        int J = searchsorted_inner(yaxis, q, n);
        float y0 = yaxis[J];
        float y1 = yaxis[J + 1];
        int j2 = (J + 2 < n) ? J + 2 : n - 1;
        float y2 = yaxis[j2];
        float dy = y1 - y0;
        float t  = (q - y0) / dy;
        float t2 = t * t, t3 = t2 * t;
        float h0 = 1.0f - 3.0f * t2 + 2.0f * t3;
        float h1 = t - 2.0f * t2 + t3;
        float h2 = 3.0f * t2 - 2.0f * t3;
        float h3 = t3 - t2;
        float r  = dy / (y2 - y1);
        float4 w;
        w.x = h0;        // weight on out[.., J]
        w.y = h2;        // weight on out[.., J+1]
        w.z = h1;        // weight on (S[J+1,k]-S[J,k])
        w.w = h3 * r;    // weight on (S[J+2,k]-S[J+1,k])
        g_yw[k] = w;
        g_yJ[k] = J;
    }
}

// One CTA per output row (b, my). Stages rows J, J+1 in smem; row J+2 read
// column-coalesced directly from global (only needed at column k).
__global__ __launch_bounds__(256) void hermite2d_kernel(
    const float* __restrict__ signal,
    float* __restrict__ out,
    int n) {
    extern __shared__ float sm[];          // 2*n floats
    float* rowJ  = sm;
    float* rowJ1 = sm + n;

    int bm = blockIdx.x;
    int b  = bm / n;
    int my = bm - b * n;

    int    J  = g_yJ[my];
    float4 yw = g_yw[my];

    const float* base = signal + ((size_t)b * n + J) * (size_t)n;   // row J
    // coalesced float4 stage of rows J and J+1
    int nv = n >> 2;
    const float4* srcJ  = reinterpret_cast<const float4*>(base);
    const float4* srcJ1 = reinterpret_cast<const float4*>(base + n);
    float4* dstJ  = reinterpret_cast<float4*>(rowJ);
    float4* dstJ1 = reinterpret_cast<float4*>(rowJ1);
    for (int i = threadIdx.x; i < nv; i += blockDim.x) {
        dstJ[i]  = srcJ[i];
        dstJ1[i] = srcJ1[i];
    }
    __syncthreads();

    const float* rowJ2 = base + 2 * (size_t)n;
    float* orow = out + ((size_t)b * n + my) * (size_t)n;

    for (int k = threadIdx.x; k < n; k += blockDim.x) {
        float4 xw = g_xw[k];
        int I = __float_as_int(xw.w);

        float oJ  = xw.x * rowJ[I]  + xw.y * rowJ[I + 1]  + xw.z * rowJ[I + 2];
        float oJ1 = xw.x * rowJ1[I] + xw.y * rowJ1[I + 1] + xw.z * rowJ1[I + 2];

        float sJk  = rowJ[k];
        float sJ1k = rowJ1[k];
        float sJ2k = __ldg(rowJ2 + k);

        float val = yw.x * oJ + yw.y * oJ1
                  + yw.z * (sJ1k - sJk)
                  + yw.w * (sJ2k - sJ1k);
        orow[k] = val;
    }
}

extern "C" void kernel_launch(void* const* d_in, const int* in_sizes, int n_in,
                              void* d_out, int out_size) {
    const float* xaxis  = (const float*)d_in[0];
    const float* yaxis  = (const float*)d_in[1];
    const float* signal = (const float*)d_in[2];
    const float* xs     = (const float*)d_in[3];
    const float* ys     = (const float*)d_in[4];
    float* out = (float*)d_out;

    int n = in_sizes[0];                 // N (square grid, Mx = My = N)
    int B = in_sizes[2] / (n * n);       // batch

    precompute_weights<<<(n + 255) / 256, 256>>>(xaxis, yaxis, xs, ys, n);

    size_t smem = 2 * (size_t)n * sizeof(float);
    hermite2d_kernel<<<B * n, 256, smem>>>(signal, out, n);
}

// round 3
// speedup vs baseline: 1.2148x; 1.2148x over previous
#include <cuda_runtime.h>
#include <cstdint>

#define MAXN 4096

// Per-x-query: wa, wb, wc, bitcast(I)
__device__ float4 g_xw[MAXN];
// Per-y-query: h0, h2, h1, h3*ratio
__device__ float4 g_yw[MAXN];
__device__ int    g_yJ[MAXN];

__device__ __forceinline__ int searchsorted_inner(const float* __restrict__ axis, float q, int n) {
    // searchsorted(axis[1:n-1], q, side='left'): smallest idx in [0, n-2] with axis[1+idx] >= q
    int lo = 0, hi = n - 2;
    while (lo < hi) {
        int mid = (lo + hi) >> 1;
        if (axis[1 + mid] < q) lo = mid + 1; else hi = mid;
    }
    return lo;
}

__global__ void precompute_weights(const float* __restrict__ xaxis,
                                   const float* __restrict__ yaxis,
                                   const float* __restrict__ xs,
                                   const float* __restrict__ ys,
                                   int n) {
    int k = blockIdx.x * blockDim.x + threadIdx.x;
    if (k >= n) return;

    // ---- x direction ----
    {
        float q = xs[k];
        int I = searchsorted_inner(xaxis, q, n);
        float x0 = xaxis[I];
        float x1 = xaxis[I + 1];
        int i2 = (I + 2 < n) ? I + 2 : n - 1;     // defensive clamp (domain keeps I+2 < n)
        float x2 = xaxis[i2];
        float dx = x1 - x0;
        float t  = (q - x0) / dx;
        float t2 = t * t, t3 = t2 * t;
        float h0 = 1.0f - 3.0f * t2 + 2.0f * t3;
        float h1 = t - 2.0f * t2 + t3;
        float h2 = 3.0f * t2 - 2.0f * t3;
        float h3 = t3 - t2;
        float r  = dx / (x2 - x1);
        float4 w;
        w.x = h0 - h1;               // weight on S[I]
        w.y = h1 + h2 - h3 * r;      // weight on S[I+1]
        w.z = h3 * r;                // weight on S[I+2]
        w.w = __int_as_float(I);
        g_xw[k] = w;
    }

    // ---- y direction ----
    {
        float q = ys[k];
        int J = searchsorted_inner(yaxis, q, n);
        float y0 = yaxis[J];
        float y1 = yaxis[J + 1];
        int j2 = (J + 2 < n) ? J + 2 : n - 1;
        float y2 = yaxis[j2];
        float dy = y1 - y0;
        float t  = (q - y0) / dy;
        float t2 = t * t, t3 = t2 * t;
        float h0 = 1.0f - 3.0f * t2 + 2.0f * t3;
        float h1 = t - 2.0f * t2 + t3;
        float h2 = 3.0f * t2 - 2.0f * t3;
        float h3 = t3 - t2;
        float r  = dy / (y2 - y1);
        float4 w;
        w.x = h0;        // weight on out[.., J]
        w.y = h2;        // weight on out[.., J+1]
        w.z = h1;        // weight on (S[J+1,k]-S[J,k])
        w.w = h3 * r;    // weight on (S[J+2,k]-S[J+1,k])
        g_yw[k] = w;
        g_yJ[k] = J;
    }
}

// One CTA per output row (b, my).
// Staging folds the y-direction combination into two per-row arrays:
//   rowC[i] = yw.x*S[J,i] + yw.y*S[J+1,i]   (only array that gets gathered)
//   rowD[i] = yw.z*(S[J+1,i]-S[J,i]) + yw.w*(S[J+2,i]-S[J+1,i])   (coalesced)
// Per element: 3 gather LDS + 1 coalesced LDS + cached g_xw LDG + STG.
__global__ __launch_bounds__(256) void hermite2d_kernel(
    const float* __restrict__ signal,
    float* __restrict__ out,
    int n) {
    extern __shared__ float sm[];          // 2*n floats
    float* rowC = sm;
    float* rowD = sm + n;

    int bm = blockIdx.x;
    int b  = bm / n;
    int my = bm - b * n;

    int    J  = g_yJ[my];
    float4 yw = g_yw[my];

    const float* base = signal + ((size_t)b * n + J) * (size_t)n;   // row J
    int nv = n >> 2;
    const float4* srcJ  = reinterpret_cast<const float4*>(base);
    const float4* srcJ1 = reinterpret_cast<const float4*>(base + n);
    const float4* srcJ2 = reinterpret_cast<const float4*>(base + 2 * (size_t)n);
    float4* dstC = reinterpret_cast<float4*>(rowC);
    float4* dstD = reinterpret_cast<float4*>(rowD);
    for (int i = threadIdx.x; i < nv; i += blockDim.x) {
        float4 a = srcJ[i];
        float4 c = srcJ1[i];
        float4 e = srcJ2[i];
        float4 C, D;
        C.x = yw.x * a.x + yw.y * c.x;
        C.y = yw.x * a.y + yw.y * c.y;
        C.z = yw.x * a.z + yw.y * c.z;
        C.w = yw.x * a.w + yw.y * c.w;
        D.x = yw.z * (c.x - a.x) + yw.w * (e.x - c.x);
        D.y = yw.z * (c.y - a.y) + yw.w * (e.y - c.y);
        D.z = yw.z * (c.z - a.z) + yw.w * (e.z - c.z);
        D.w = yw.z * (c.w - a.w) + yw.w * (e.w - c.w);
        dstC[i] = C;
        dstD[i] = D;
    }
    __syncthreads();

    float* orow = out + ((size_t)b * n + my) * (size_t)n;

    for (int k = threadIdx.x; k < n; k += blockDim.x) {
        float4 xw = g_xw[k];
        int I = __float_as_int(xw.w);

        float val = xw.x * rowC[I] + xw.y * rowC[I + 1] + xw.z * rowC[I + 2]
                  + rowD[k];
        orow[k] = val;
    }
}

extern "C" void kernel_launch(void* const* d_in, const int* in_sizes, int n_in,
                              void* d_out, int out_size) {
    const float* xaxis  = (const float*)d_in[0];
    const float* yaxis  = (const float*)d_in[1];
    const float* signal = (const float*)d_in[2];
    const float* xs     = (const float*)d_in[3];
    const float* ys     = (const float*)d_in[4];
    float* out = (float*)d_out;

    int n = in_sizes[0];                 // N (square grid, Mx = My = N)
    int B = in_sizes[2] / (n * n);       // batch

    precompute_weights<<<(n + 255) / 256, 256>>>(xaxis, yaxis, xs, ys, n);

    size_t smem = 2 * (size_t)n * sizeof(float);
    hermite2d_kernel<<<B * n, 256, smem>>>(signal, out, n);
}